// round 16
// baseline (speedup 1.0000x reference)
#include <cuda_runtime.h>
#include <cuda_fp16.h>
#include <cstdint>

#define BATCH   16
#define DIM     256
#define HWSZ    4096
#define NROWS   65536
#define NCODE   1024
#define XELEMS  16777216
#define ENCELEMS 67108864
#define MARGIN  4e-3f
#define MAXCAND 32

typedef unsigned long long u64;

// ---------------- scratch (device globals) ----------------
__device__ int      g_idx[NROWS];
__device__ int      g_hist[NCODE];
__device__ float    g_cbsq[NCODE];
__device__ float    g_insq[NROWS];
__device__ double   g_losssum;
__device__ float    g_xt[NROWS * 256];        // transposed x, fp32 [n][d]
__device__ uint32_t g_ahi[NROWS * 128];       // fp16x2 pairs, [n][d/2]
__device__ uint32_t g_bf[NCODE * 128];        // codebook fp16, MMA B-fragment order
__device__ int      g_cnt[NROWS];             // candidate counts
__device__ uint32_t g_cand[NROWS * MAXCAND];  // candidate code ids

// ---------------- PTX helpers (baseline sm_80 features only) ----------------
__device__ __forceinline__ uint32_t smem_u32(const void* p) {
    uint32_t a;
    asm("{ .reg .u64 t; cvta.to.shared.u64 t, %1; cvt.u32.u64 %0, t; }" : "=r"(a) : "l"(p));
    return a;
}
#define LDSM4(r0, r1, r2, r3, a) \
    asm volatile("ldmatrix.sync.aligned.m8n8.x4.shared.b16 {%0,%1,%2,%3}, [%4];" \
        : "=r"(r0), "=r"(r1), "=r"(r2), "=r"(r3) : "r"(a))
#define MMA16816(d, a0, a1, a2, a3, b0, b1) \
    asm volatile("mma.sync.aligned.m16n8k16.row.col.f32.f16.f16.f32 " \
        "{%0,%1,%2,%3}, {%4,%5,%6,%7}, {%8,%9}, {%0,%1,%2,%3};" \
        : "+f"((d)[0]), "+f"((d)[1]), "+f"((d)[2]), "+f"((d)[3]) \
        : "r"(a0), "r"(a1), "r"(a2), "r"(a3), "r"(b0), "r"(b1))
#define CP_ASYNC16(dst, src) \
    asm volatile("cp.async.cg.shared.global [%0], [%1], 16;" :: "r"(dst), "l"(src))
#define CP_COMMIT() asm volatile("cp.async.commit_group;" ::: "memory")
#define CP_WAIT0()  asm volatile("cp.async.wait_group 0;" ::: "memory")

// ---------------- SMEM layout for k_mma (dynamic) ----------------
#define SM_AHI    0          // 65536: A_hi resident, 4 tiles of [128][64 fp16]
#define SM_CBSQ   65536      // 4096
#define SM_INSQ   69632      // 512
#define SM_ROWMIN 70144      // 512 (float bits)
#define SM_CNT    70656      // 512
#define SM_CAND   71168      // 128*32*4 = 16384
#define SM_TOTAL  87552

// ---------------- prep: zero accum + codebook fragments + norms ----------------
__global__ void k_prep(const float* __restrict__ cb) {
    int i = blockIdx.x * 256 + threadIdx.x;      // over NCODE*128 u32 (d-pairs)
    if (i == 0) g_losssum = 0.0;
    int k = i >> 7;
    int d = (i & 127) * 2;
    float2 v = *reinterpret_cast<const float2*>(cb + (size_t)k * DIM + d);
    __half h0 = __float2half_rn(v.x);
    __half h1 = __float2half_rn(v.y);
    int nt = k >> 7, cc = k & 127;
    int n8g = cc >> 3;
    int lane = ((cc & 7) << 2) | ((d & 7) >> 1);
    int kstep = d >> 4;
    int word = (d >> 3) & 1;
    uint32_t idx = (uint32_t)((((nt * 16 + kstep) * 16 + n8g) * 32 + lane) * 2 + word);
    g_bf[idx] = ((uint32_t)__half_as_ushort(h1) << 16) | __half_as_ushort(h0);
    if (i < NCODE) {
        g_hist[i] = 0;
        const float4* p = reinterpret_cast<const float4*>(cb + (size_t)i * DIM);
        float s = 0.f;
        #pragma unroll 8
        for (int dd = 0; dd < DIM / 4; dd++) {
            float4 q = p[dd];
            s += q.x * q.x; s += q.y * q.y; s += q.z * q.z; s += q.w * q.w;
        }
        g_cbsq[i] = s;
    }
}

// x NCHW -> a_hi [n][d] fp16x2 + g_xt fp32 + per-row |x|^2 (sequential-d)
__global__ void __launch_bounds__(256) k_split_x(const float* __restrict__ x) {
    __shared__ float s[256 * 33];
    const int t  = threadIdx.x;
    const int n0 = blockIdx.x * 32;
    const int b  = n0 >> 12;
    const int hw0 = n0 & 4095;
    const float* xb = x + (size_t)b * DIM * HWSZ + hw0;

    #pragma unroll
    for (int i = 0; i < 32; i++) {
        int lin = i * 256 + t;
        int d = lin >> 5, hw = lin & 31;
        s[d * 33 + hw] = xb[(size_t)d * HWSZ + hw];
    }
    __syncthreads();

    if (t < 32) {   // in_sq, sequential over d
        float acc = 0.f;
        #pragma unroll 8
        for (int d = 0; d < 256; d++) {
            float v = s[d * 33 + t];
            acc += v * v;
        }
        g_insq[n0 + t] = acc;
    }

    #pragma unroll
    for (int j = 0; j < 16; j++) {
        int lin = j * 256 + t;              // over 32*128 u32 outputs
        int nl = lin >> 7, c = lin & 127;
        float v0 = s[(2 * c) * 33 + nl];
        float v1 = s[(2 * c + 1) * 33 + nl];
        __half h0 = __float2half_rn(v0);
        __half h1 = __float2half_rn(v1);
        size_t o = (size_t)(n0 + nl) * 128 + c;
        g_ahi[o] = ((uint32_t)__half_as_ushort(h1) << 16) | __half_as_ushort(h0);
        float2* xt = reinterpret_cast<float2*>(&g_xt[(size_t)(n0 + nl) * 256 + 2 * c]);
        *xt = make_float2(v0, v1);
    }
}

// ---------------- mma.sync filter kernel (candidates -> global) ----------------
__global__ void __launch_bounds__(512, 1) k_mma() {
    extern __shared__ __align__(1024) char smem[];
    const uint32_t sb = smem_u32(smem);
    const int t    = threadIdx.x;
    const int lane = t & 31;
    const int wid  = t >> 5;
    const int warp_m = wid >> 2;        // 0..3  (m32 each)
    const int warp_n = wid & 3;         // 0..3  (n32 each)
    const int n0   = blockIdx.x * 128;

    float* s_cbsq = reinterpret_cast<float*>(smem + SM_CBSQ);
    float* s_insq = reinterpret_cast<float*>(smem + SM_INSQ);
    uint32_t* s_rowmin = reinterpret_cast<uint32_t*>(smem + SM_ROWMIN);
    int* s_cnt = reinterpret_cast<int*>(smem + SM_CNT);
    uint32_t* s_cand = reinterpret_cast<uint32_t*>(smem + SM_CAND);

    s_cbsq[t] = g_cbsq[t];
    s_cbsq[t + 512] = g_cbsq[t + 512];
    if (t < 128) {
        s_insq[t] = g_insq[n0 + t];
        s_rowmin[t] = 0x7F800000u;   // +inf
        s_cnt[t] = 0;
    }

    // ---- A_hi resident via cp.async (4096 16B segments; 8 per thread)
    #pragma unroll
    for (int i = 0; i < 8; i++) {
        int s = i * 512 + t;
        int q = s >> 10, rem = s & 1023;
        int row = rem >> 3, j = rem & 7;
        uint32_t dst = sb + SM_AHI + q * 16384 + row * 128 +
                       ((j * 16) ^ ((row & 7) << 4));
        const uint32_t* src = g_ahi + (size_t)(n0 + row) * 128 + q * 32 + j * 4;
        CP_ASYNC16(dst, src);
    }
    CP_COMMIT();

    // ---- per-lane ldmatrix address components (A only)
    uint32_t arow[2], arx[2];
    #pragma unroll
    for (int mt = 0; mt < 2; mt++) {
        int r = warp_m * 32 + mt * 16 + (lane & 15);
        arow[mt] = (uint32_t)r * 128;
        arx[mt]  = (uint32_t)((r & 7) << 4);
    }
    const uint32_t ahalf = (uint32_t)((lane >> 4) * 16);

    float insqr[4];
    float acc[2][4][4];   // [mt][n8][c]

    const u64* bbase =
        reinterpret_cast<const u64*>(g_bf) + (warp_n * 4) * 32 + lane;

    CP_WAIT0();
    __syncthreads();      // A + cbsq/insq/rowmin/cnt visible

    #pragma unroll
    for (int i = 0; i < 4; i++) {
        int mt = i >> 1, hf = i & 1;
        insqr[i] = s_insq[warp_m * 32 + mt * 16 + hf * 8 + (lane >> 2)];
    }

    for (int nt = 0; nt < 8; nt++) {
        #pragma unroll
        for (int mt = 0; mt < 2; mt++)
            #pragma unroll
            for (int n8 = 0; n8 < 4; n8++)
                #pragma unroll
                for (int i = 0; i < 4; i++) acc[mt][n8][i] = 0.f;

        const u64* bp = bbase + (size_t)nt * 16 * 16 * 32;
        u64 bc[4], bn[4];
        #pragma unroll
        for (int n8 = 0; n8 < 4; n8++) bc[n8] = __ldg(bp + n8 * 32);

        #pragma unroll
        for (int ks = 0; ks < 16; ks++) {
            if (ks < 15) {
                const u64* np = bp + (ks + 1) * 512;
                #pragma unroll
                for (int n8 = 0; n8 < 4; n8++) bn[n8] = __ldg(np + n8 * 32);
            }
            const uint32_t qoff = (uint32_t)((ks >> 2) * 16384);
            const uint32_t kb = (uint32_t)((ks & 3) * 32);
            uint32_t a[2][4];
            #pragma unroll
            for (int mt = 0; mt < 2; mt++)
                LDSM4(a[mt][0], a[mt][1], a[mt][2], a[mt][3],
                      sb + SM_AHI + qoff + arow[mt] + ((kb + ahalf) ^ arx[mt]));
            #pragma unroll
            for (int mt = 0; mt < 2; mt++)
                #pragma unroll
                for (int n8 = 0; n8 < 4; n8++)
                    MMA16816(acc[mt][n8], a[mt][0], a[mt][1], a[mt][2], a[mt][3],
                             (uint32_t)bc[n8], (uint32_t)(bc[n8] >> 32));
            #pragma unroll
            for (int n8 = 0; n8 < 4; n8++) bc[n8] = bn[n8];
        }

        // ---- epilogue: compute all 32 dists ONCE, fold, guarded append ----
        const int colbase = nt * 128 + warp_n * 32 + (lane & 3) * 2;
        float dl[32];     // [(mt*2+hf)*8 + n8*2 + ci]
        float mnl[4];
        #pragma unroll
        for (int mt = 0; mt < 2; mt++) {
            #pragma unroll
            for (int hf = 0; hf < 2; hf++) {
                const float iq = insqr[mt * 2 + hf];
                float mn = __uint_as_float(0x7F800000u);
                #pragma unroll
                for (int n8 = 0; n8 < 4; n8++) {
                    #pragma unroll
                    for (int ci = 0; ci < 2; ci++) {
                        float tq = iq + s_cbsq[colbase + n8 * 8 + ci];
                        float dist = tq - 2.0f * acc[mt][n8][hf * 2 + ci];
                        dl[(mt * 2 + hf) * 8 + n8 * 2 + ci] = dist;
                        mn = fminf(mn, dist);
                    }
                }
                mnl[mt * 2 + hf] = mn;
                float o1 = __shfl_xor_sync(0xFFFFFFFFu, mn, 1);
                mn = fminf(mn, o1);
                float o2 = __shfl_xor_sync(0xFFFFFFFFu, mn, 2);
                mn = fminf(mn, o2);
                if ((lane & 3) == 0) {
                    int row = warp_m * 32 + mt * 16 + hf * 8 + (lane >> 2);
                    if (mn < __uint_as_float(s_rowmin[row]))
                        atomicMin(&s_rowmin[row], __float_as_uint(mn));
                }
            }
        }
        #pragma unroll
        for (int i = 0; i < 4; i++) {
            const int mt = i >> 1, hf = i & 1;
            const int row = warp_m * 32 + mt * 16 + hf * 8 + (lane >> 2);
            const float thr = __uint_as_float(s_rowmin[row]) + MARGIN;
            if (mnl[i] < thr) {
                #pragma unroll
                for (int j = 0; j < 8; j++) {
                    if (dl[i * 8 + j] < thr) {
                        int pos = atomicAdd(&s_cnt[row], 1);
                        if (pos < MAXCAND)
                            s_cand[row * MAXCAND + pos] =
                                (uint32_t)(colbase + (j >> 1) * 8 + (j & 1));
                    }
                }
            }
        }
    }
    __syncthreads();

    // ---- dump candidates + counts to global (coalesced) ----
    if (t < 128) g_cnt[n0 + t] = s_cnt[t];
    #pragma unroll
    for (int i = 0; i < (128 * MAXCAND) / 512; i++)
        g_cand[(size_t)n0 * MAXCAND + i * 512 + t] = s_cand[i * 512 + t];
}

// ---------------- exact rescore: fully-coalesced batch staging ----------------
// Block owns 32 rows. Stage the 32 xt rows coalesced; pack a block queue of
// (row,col) pairs (cap 32*MAXCAND, cannot overflow); per 32-entry batch, stage
// the 32 candidate cb rows coalesced into shared, then run 32 chains in
// parallel (entry w*4+lane on lanes 0..3 of each of 8 warps) reading ONLY
// shared — the chain keeps the bit-identical sequential d=0..255 fmaf order.
// cnt==1 rows short-circuit; cnt>MAXCAND rows get a cooperative full scan.
#define RSQ_CAP (32 * MAXCAND)
#define RS_XT   0
#define RS_CB   (32 * 257)
#define RS_Q    (2 * 32 * 257)                    // u32 [RSQ_CAP]
#define RS_BEST (RS_Q + RSQ_CAP)                  // u64 [32] (8B aligned)
#define RS_META (RS_BEST + 2 * 32)                // int: qtot, nfull, full[32], cnt[32]
#define RS_SMEM ((RS_META + 2 + 32 + 32) * 4)

__global__ void __launch_bounds__(256) k_rescore(const float* __restrict__ cb) {
    extern __shared__ float rs[];
    float* xt_sh = rs + RS_XT;                    // [32][257]
    float* cb_sh = rs + RS_CB;                    // [32][257]
    uint32_t* queue = reinterpret_cast<uint32_t*>(rs + RS_Q);
    u64* s_best = reinterpret_cast<u64*>(rs + RS_BEST);
    int* s_meta = reinterpret_cast<int*>(rs + RS_META);   // [0]=qtot [1]=nfull
    int* s_full = s_meta + 2;
    int* s_cnts = s_full + 32;

    const int t = threadIdx.x;
    const int w = t >> 5;
    const int lane = t & 31;
    const int n0 = blockIdx.x * 32;

    if (t == 0) { s_meta[0] = 0; s_meta[1] = 0; }
    if (t < 32) s_best[t] = ~0ull;
    __syncthreads();

    // stage 32 xt rows (coalesced float4)
    #pragma unroll
    for (int j = 0; j < 8; j++) {
        int f4 = j * 256 + t;
        int row = f4 >> 6, q4 = f4 & 63;
        float4 v = *reinterpret_cast<const float4*>(
            &g_xt[(size_t)(n0 + row) * 256 + q4 * 4]);
        float* dst = &xt_sh[row * 257 + q4 * 4];
        dst[0] = v.x; dst[1] = v.y; dst[2] = v.z; dst[3] = v.w;
    }

    // classify + pack queue
    if (t < 32) {
        int n = n0 + t;
        int cnt = g_cnt[n];
        s_cnts[t] = cnt;
        if (cnt == 1) {
            int kbest = (int)g_cand[(size_t)n * MAXCAND];
            g_idx[n] = kbest;
            atomicAdd(&g_hist[kbest], 1);
        } else if (cnt <= MAXCAND) {
            int base = atomicAdd(&s_meta[0], cnt);
            for (int i = 0; i < cnt; i++)
                queue[base + i] = ((uint32_t)t << 10) |
                                  g_cand[(size_t)n * MAXCAND + i];
        } else {
            int fi = atomicAdd(&s_meta[1], 1);
            s_full[fi] = t;
        }
    }
    __syncthreads();

    const int qtot = s_meta[0];
    for (int b0 = 0; b0 < qtot; b0 += 32) {
        const int nb = min(32, qtot - b0);
        // stage nb cb rows coalesced: 2048 float4 over 256 threads
        #pragma unroll
        for (int i = 0; i < 8; i++) {
            int j = i * 256 + t;
            int ci = j >> 6, f4 = j & 63;
            if (ci < nb) {
                int col = (int)(queue[b0 + ci] & 1023u);
                float4 v = __ldg(reinterpret_cast<const float4*>(
                    cb + (size_t)col * 256 + f4 * 4));
                float* dst = &cb_sh[ci * 257 + f4 * 4];
                dst[0] = v.x; dst[1] = v.y; dst[2] = v.z; dst[3] = v.w;
            }
        }
        __syncthreads();
        // 32 chains: entry ei = w*4 + lane on lanes 0..3 of each warp
        const int ei = w * 4 + lane;
        if (lane < 4 && ei < nb) {
            uint32_t ent = queue[b0 + ei];
            int rl = ent >> 10, col = (int)(ent & 1023u);
            const float* xr = &xt_sh[rl * 257];
            const float* cr = &cb_sh[ei * 257];
            float dot = 0.f;
            #pragma unroll 16
            for (int d = 0; d < 256; d++) dot = fmaf(xr[d], cr[d], dot);
            float tq = g_insq[n0 + rl] + g_cbsq[col];
            float dist = tq - 2.0f * dot;
            u64 k = ((u64)__float_as_uint(dist) << 32) | (unsigned)col;
            atomicMin(&s_best[rl], k);
        }
        __syncthreads();
    }

    // full-scan fallback rows (block-cooperative; rare/never)
    const int nfull = s_meta[1];
    for (int fi = 0; fi < nfull; fi++) {
        int rl = s_full[fi];
        const float* xr = &xt_sh[rl * 257];
        const float iq = g_insq[n0 + rl];
        u64 best = ~0ull;
        for (int col = t; col < NCODE; col += 256) {
            const float4* cr4 = reinterpret_cast<const float4*>(cb + (size_t)col * 256);
            float dot = 0.f;
            #pragma unroll 8
            for (int d4 = 0; d4 < 64; d4++) {
                float4 c4 = __ldg(cr4 + d4);
                dot = fmaf(xr[d4 * 4 + 0], c4.x, dot);
                dot = fmaf(xr[d4 * 4 + 1], c4.y, dot);
                dot = fmaf(xr[d4 * 4 + 2], c4.z, dot);
                dot = fmaf(xr[d4 * 4 + 3], c4.w, dot);
            }
            float dist = (iq + g_cbsq[col]) - 2.0f * dot;
            u64 k = ((u64)__float_as_uint(dist) << 32) | (unsigned)col;
            if (k < best) best = k;
        }
        if (best != ~0ull) atomicMin(&s_best[rl], best);
    }
    if (nfull > 0) __syncthreads();

    if (t < 32 && s_cnts[t] >= 2) {
        int kbest = (int)(unsigned)(s_best[t] & 0xFFFFFFFFull);
        g_idx[n0 + t] = kbest;
        atomicAdd(&g_hist[kbest], 1);
    }
}

// ---------------- outputs ----------------
__global__ void k_ones(float* __restrict__ enc) {
    int n = blockIdx.x * 256 + threadIdx.x;
    enc[(size_t)n * NCODE + g_idx[n]] = 1.0f;
}

// coalesced xq: block = (b, 32 hw) x 256 d; codebook rows staged in shared.
__global__ void __launch_bounds__(256) k_xq2(const float* __restrict__ x,
                                             const float* __restrict__ cb,
                                             float* __restrict__ outb) {
    __shared__ float cbs[32 * 261];
    __shared__ int idxs[32];
    __shared__ float warpsum[8];
    const int t = threadIdx.x;
    const int b = blockIdx.x >> 7;
    const int hw0 = (blockIdx.x & 127) << 5;
    const int n0 = (b << 12) + hw0;
    if (t < 32) idxs[t] = g_idx[n0 + t];
    __syncthreads();
    #pragma unroll
    for (int j = 0; j < 8; j++) {
        int lin = j * 256 + t;               // 2048 = 32 rows x 64 float4
        int row = lin >> 6, f4 = lin & 63;
        float4 v = *reinterpret_cast<const float4*>(
            &cb[(size_t)idxs[row] * 256 + f4 * 4]);
        float* dst = &cbs[row * 261 + f4 * 4];
        dst[0] = v.x; dst[1] = v.y; dst[2] = v.z; dst[3] = v.w;
    }
    __syncthreads();
    float lsum = 0.f;
    #pragma unroll
    for (int i2 = 0; i2 < 8; i2++) {
        int f4 = i2 * 256 + t;               // 2048 float4 tiles
        int d = f4 >> 3, hw4 = (f4 & 7) * 4;
        size_t gi = (((size_t)b * 256 + d) << 12) + hw0 + hw4;
        float4 xv = *reinterpret_cast<const float4*>(x + gi);
        float q0 = cbs[(hw4 + 0) * 261 + d];
        float q1 = cbs[(hw4 + 1) * 261 + d];
        float q2 = cbs[(hw4 + 2) * 261 + d];
        float q3 = cbs[(hw4 + 3) * 261 + d];
        float d0 = q0 - xv.x, d1 = q1 - xv.y, d2 = q2 - xv.z, d3 = q3 - xv.w;
        lsum += d0 * d0; lsum += d1 * d1; lsum += d2 * d2; lsum += d3 * d3;
        outb[gi]     = xv.x + d0;
        outb[gi + 1] = xv.y + d1;
        outb[gi + 2] = xv.z + d2;
        outb[gi + 3] = xv.w + d3;
    }
    #pragma unroll
    for (int off = 16; off; off >>= 1) lsum += __shfl_down_sync(0xFFFFFFFFu, lsum, off);
    if ((t & 31) == 0) warpsum[t >> 5] = lsum;
    __syncthreads();
    if (t == 0) {
        float s = 0.f;
        #pragma unroll
        for (int ww = 0; ww < 8; ww++) s += warpsum[ww];
        atomicAdd(&g_losssum, (double)s);
    }
}

__global__ void k_fin(float* __restrict__ out_loss, float* __restrict__ out_perp) {
    __shared__ float sred[32];
    int t = threadIdx.x;
    float e_mean = (float)g_hist[t] * (1.0f / 65536.0f);
    float term = e_mean * logf(e_mean + 1e10f);
    #pragma unroll
    for (int off = 16; off; off >>= 1) term += __shfl_down_sync(0xFFFFFFFFu, term, off);
    if ((t & 31) == 0) sred[t >> 5] = term;
    __syncthreads();
    if (t < 32) {
        float v = sred[t];
        #pragma unroll
        for (int off = 16; off; off >>= 1) v += __shfl_down_sync(0xFFFFFFFFu, v, off);
        if (t == 0) {
            if (out_perp) *out_perp = expf(-v);
            if (out_loss) {
                float mse = (float)(g_losssum * (1.0 / 16777216.0));
                *out_loss = mse + 0.25f * mse;
            }
        }
    }
}

extern "C" void kernel_launch(void* const* d_in, const int* in_sizes, int n_in,
                              void* d_out, int out_size) {
    const float* x  = (const float*)d_in[0];
    const float* cb = (const float*)d_in[1];
    if (n_in >= 2 && in_sizes[0] == NCODE * DIM) {
        x  = (const float*)d_in[1];
        cb = (const float*)d_in[0];
    }

    float* out = (float*)d_out;
    float *o_loss = nullptr, *o_xq = nullptr, *o_perp = nullptr, *o_enc = nullptr;
    if (out_size == XELEMS) {
        o_xq = out;
    } else if (out_size == ENCELEMS) {
        o_enc = out;
    } else if (out_size == 2) {
        o_loss = out; o_perp = out + 1;
    } else {
        o_loss = out;
        o_xq   = out + 1;
        o_perp = out + 1 + XELEMS;
        o_enc  = out + 2 + XELEMS;
    }

    cudaFuncSetAttribute(k_mma, cudaFuncAttributeMaxDynamicSharedMemorySize, SM_TOTAL);
    cudaFuncSetAttribute(k_rescore, cudaFuncAttributeMaxDynamicSharedMemorySize, RS_SMEM);

    // k_rescore stays the 4th kernel launch (ncu capture lands on launch #4)
    // to verify the coalesced batch-staging rework.
    k_prep<<<512, 256>>>(cb);
    k_split_x<<<NROWS / 32, 256>>>(x);
    k_mma<<<NROWS / 128, 512, SM_TOTAL>>>();
    k_rescore<<<NROWS / 32, 256, RS_SMEM>>>(cb);
    if (o_enc) {
        cudaMemsetAsync(o_enc, 0, (size_t)ENCELEMS * sizeof(float));
        k_ones<<<NROWS / 256, 256>>>(o_enc);
    }
    if (o_xq) k_xq2<<<2048, 256>>>(x, cb, o_xq);
    k_fin<<<1, 1024>>>(o_loss, o_perp);
}

// round 17
// speedup vs baseline: 1.3332x; 1.3332x over previous
#include <cuda_runtime.h>
#include <cuda_fp16.h>
#include <cstdint>

#define BATCH   16
#define DIM     256
#define HWSZ    4096
#define NROWS   65536
#define NCODE   1024
#define XELEMS  16777216
#define ENCELEMS 67108864
#define MARGIN  4e-3f
#define MAXCAND 32

typedef unsigned long long u64;

// ---------------- scratch (device globals) ----------------
__device__ int      g_idx[NROWS];
__device__ int      g_hist[NCODE];
__device__ float    g_cbsq[NCODE];
__device__ float    g_insq[NROWS];
__device__ double   g_losssum;
__device__ float    g_xt[NROWS * 256];        // transposed x, fp32 [n][d]
__device__ uint32_t g_ahi[NROWS * 128];       // fp16x2 pairs, [n][d/2]
__device__ uint32_t g_bf[NCODE * 128];        // codebook fp16, MMA B-fragment order
__device__ int      g_cnt[NROWS];             // candidate counts
__device__ uint32_t g_cand[NROWS * MAXCAND];  // candidate code ids

// ---------------- PTX helpers (baseline sm_80 features only) ----------------
__device__ __forceinline__ uint32_t smem_u32(const void* p) {
    uint32_t a;
    asm("{ .reg .u64 t; cvta.to.shared.u64 t, %1; cvt.u32.u64 %0, t; }" : "=r"(a) : "l"(p));
    return a;
}
#define LDSM4(r0, r1, r2, r3, a) \
    asm volatile("ldmatrix.sync.aligned.m8n8.x4.shared.b16 {%0,%1,%2,%3}, [%4];" \
        : "=r"(r0), "=r"(r1), "=r"(r2), "=r"(r3) : "r"(a))
#define MMA16816(d, a0, a1, a2, a3, b0, b1) \
    asm volatile("mma.sync.aligned.m16n8k16.row.col.f32.f16.f16.f32 " \
        "{%0,%1,%2,%3}, {%4,%5,%6,%7}, {%8,%9}, {%0,%1,%2,%3};" \
        : "+f"((d)[0]), "+f"((d)[1]), "+f"((d)[2]), "+f"((d)[3]) \
        : "r"(a0), "r"(a1), "r"(a2), "r"(a3), "r"(b0), "r"(b1))
#define CP_ASYNC16(dst, src) \
    asm volatile("cp.async.cg.shared.global [%0], [%1], 16;" :: "r"(dst), "l"(src))
#define CP_COMMIT() asm volatile("cp.async.commit_group;" ::: "memory")
#define CP_WAIT0()  asm volatile("cp.async.wait_group 0;" ::: "memory")

// ---------------- SMEM layout for k_mma (dynamic) ----------------
#define SM_AHI    0          // 65536: A_hi resident, 4 tiles of [128][64 fp16]
#define SM_CBSQ   65536      // 4096
#define SM_INSQ   69632      // 512
#define SM_ROWMIN 70144      // 512 (float bits)
#define SM_CNT    70656      // 512
#define SM_CAND   71168      // 128*32*4 = 16384
#define SM_TOTAL  87552

// ---------------- prep: zero accum + codebook fragments + norms ----------------
__global__ void k_prep(const float* __restrict__ cb) {
    int i = blockIdx.x * 256 + threadIdx.x;      // over NCODE*128 u32 (d-pairs)
    if (i == 0) g_losssum = 0.0;
    int k = i >> 7;
    int d = (i & 127) * 2;
    float2 v = *reinterpret_cast<const float2*>(cb + (size_t)k * DIM + d);
    __half h0 = __float2half_rn(v.x);
    __half h1 = __float2half_rn(v.y);
    int nt = k >> 7, cc = k & 127;
    int n8g = cc >> 3;
    int lane = ((cc & 7) << 2) | ((d & 7) >> 1);
    int kstep = d >> 4;
    int word = (d >> 3) & 1;
    uint32_t idx = (uint32_t)((((nt * 16 + kstep) * 16 + n8g) * 32 + lane) * 2 + word);
    g_bf[idx] = ((uint32_t)__half_as_ushort(h1) << 16) | __half_as_ushort(h0);
    if (i < NCODE) {
        g_hist[i] = 0;
        const float4* p = reinterpret_cast<const float4*>(cb + (size_t)i * DIM);
        float s = 0.f;
        #pragma unroll 8
        for (int dd = 0; dd < DIM / 4; dd++) {
            float4 q = p[dd];
            s += q.x * q.x; s += q.y * q.y; s += q.z * q.z; s += q.w * q.w;
        }
        g_cbsq[i] = s;
    }
}

// x NCHW -> a_hi [n][d] fp16x2 + g_xt fp32 + per-row |x|^2 (sequential-d)
__global__ void __launch_bounds__(256) k_split_x(const float* __restrict__ x) {
    __shared__ float s[256 * 33];
    const int t  = threadIdx.x;
    const int n0 = blockIdx.x * 32;
    const int b  = n0 >> 12;
    const int hw0 = n0 & 4095;
    const float* xb = x + (size_t)b * DIM * HWSZ + hw0;

    #pragma unroll
    for (int i = 0; i < 32; i++) {
        int lin = i * 256 + t;
        int d = lin >> 5, hw = lin & 31;
        s[d * 33 + hw] = xb[(size_t)d * HWSZ + hw];
    }
    __syncthreads();

    if (t < 32) {   // in_sq, sequential over d
        float acc = 0.f;
        #pragma unroll 8
        for (int d = 0; d < 256; d++) {
            float v = s[d * 33 + t];
            acc += v * v;
        }
        g_insq[n0 + t] = acc;
    }

    #pragma unroll
    for (int j = 0; j < 16; j++) {
        int lin = j * 256 + t;              // over 32*128 u32 outputs
        int nl = lin >> 7, c = lin & 127;
        float v0 = s[(2 * c) * 33 + nl];
        float v1 = s[(2 * c + 1) * 33 + nl];
        __half h0 = __float2half_rn(v0);
        __half h1 = __float2half_rn(v1);
        size_t o = (size_t)(n0 + nl) * 128 + c;
        g_ahi[o] = ((uint32_t)__half_as_ushort(h1) << 16) | __half_as_ushort(h0);
        float2* xt = reinterpret_cast<float2*>(&g_xt[(size_t)(n0 + nl) * 256 + 2 * c]);
        *xt = make_float2(v0, v1);
    }
}

// ---------------- mma.sync filter kernel (candidates -> global) ----------------
__global__ void __launch_bounds__(512, 1) k_mma() {
    extern __shared__ __align__(1024) char smem[];
    const uint32_t sb = smem_u32(smem);
    const int t    = threadIdx.x;
    const int lane = t & 31;
    const int wid  = t >> 5;
    const int warp_m = wid >> 2;        // 0..3  (m32 each)
    const int warp_n = wid & 3;         // 0..3  (n32 each)
    const int n0   = blockIdx.x * 128;

    float* s_cbsq = reinterpret_cast<float*>(smem + SM_CBSQ);
    float* s_insq = reinterpret_cast<float*>(smem + SM_INSQ);
    uint32_t* s_rowmin = reinterpret_cast<uint32_t*>(smem + SM_ROWMIN);
    int* s_cnt = reinterpret_cast<int*>(smem + SM_CNT);
    uint32_t* s_cand = reinterpret_cast<uint32_t*>(smem + SM_CAND);

    s_cbsq[t] = g_cbsq[t];
    s_cbsq[t + 512] = g_cbsq[t + 512];
    if (t < 128) {
        s_insq[t] = g_insq[n0 + t];
        s_rowmin[t] = 0x7F800000u;   // +inf
        s_cnt[t] = 0;
    }

    // ---- A_hi resident via cp.async (4096 16B segments; 8 per thread)
    #pragma unroll
    for (int i = 0; i < 8; i++) {
        int s = i * 512 + t;
        int q = s >> 10, rem = s & 1023;
        int row = rem >> 3, j = rem & 7;
        uint32_t dst = sb + SM_AHI + q * 16384 + row * 128 +
                       ((j * 16) ^ ((row & 7) << 4));
        const uint32_t* src = g_ahi + (size_t)(n0 + row) * 128 + q * 32 + j * 4;
        CP_ASYNC16(dst, src);
    }
    CP_COMMIT();

    // ---- per-lane ldmatrix address components (A only)
    uint32_t arow[2], arx[2];
    #pragma unroll
    for (int mt = 0; mt < 2; mt++) {
        int r = warp_m * 32 + mt * 16 + (lane & 15);
        arow[mt] = (uint32_t)r * 128;
        arx[mt]  = (uint32_t)((r & 7) << 4);
    }
    const uint32_t ahalf = (uint32_t)((lane >> 4) * 16);

    float insqr[4];
    float acc[2][4][4];   // [mt][n8][c]

    const u64* bbase =
        reinterpret_cast<const u64*>(g_bf) + (warp_n * 4) * 32 + lane;

    CP_WAIT0();
    __syncthreads();      // A + cbsq/insq/rowmin/cnt visible

    #pragma unroll
    for (int i = 0; i < 4; i++) {
        int mt = i >> 1, hf = i & 1;
        insqr[i] = s_insq[warp_m * 32 + mt * 16 + hf * 8 + (lane >> 2)];
    }

    for (int nt = 0; nt < 8; nt++) {
        #pragma unroll
        for (int mt = 0; mt < 2; mt++)
            #pragma unroll
            for (int n8 = 0; n8 < 4; n8++)
                #pragma unroll
                for (int i = 0; i < 4; i++) acc[mt][n8][i] = 0.f;

        const u64* bp = bbase + (size_t)nt * 16 * 16 * 32;
        u64 bc[4], bn[4];
        #pragma unroll
        for (int n8 = 0; n8 < 4; n8++) bc[n8] = __ldg(bp + n8 * 32);

        #pragma unroll
        for (int ks = 0; ks < 16; ks++) {
            if (ks < 15) {
                const u64* np = bp + (ks + 1) * 512;
                #pragma unroll
                for (int n8 = 0; n8 < 4; n8++) bn[n8] = __ldg(np + n8 * 32);
            }
            const uint32_t qoff = (uint32_t)((ks >> 2) * 16384);
            const uint32_t kb = (uint32_t)((ks & 3) * 32);
            uint32_t a[2][4];
            #pragma unroll
            for (int mt = 0; mt < 2; mt++)
                LDSM4(a[mt][0], a[mt][1], a[mt][2], a[mt][3],
                      sb + SM_AHI + qoff + arow[mt] + ((kb + ahalf) ^ arx[mt]));
            #pragma unroll
            for (int mt = 0; mt < 2; mt++)
                #pragma unroll
                for (int n8 = 0; n8 < 4; n8++)
                    MMA16816(acc[mt][n8], a[mt][0], a[mt][1], a[mt][2], a[mt][3],
                             (uint32_t)bc[n8], (uint32_t)(bc[n8] >> 32));
            #pragma unroll
            for (int n8 = 0; n8 < 4; n8++) bc[n8] = bn[n8];
        }

        // ---- epilogue: compute all 32 dists ONCE, fold, guarded append ----
        const int colbase = nt * 128 + warp_n * 32 + (lane & 3) * 2;
        float dl[32];     // [(mt*2+hf)*8 + n8*2 + ci]
        float mnl[4];
        #pragma unroll
        for (int mt = 0; mt < 2; mt++) {
            #pragma unroll
            for (int hf = 0; hf < 2; hf++) {
                const float iq = insqr[mt * 2 + hf];
                float mn = __uint_as_float(0x7F800000u);
                #pragma unroll
                for (int n8 = 0; n8 < 4; n8++) {
                    #pragma unroll
                    for (int ci = 0; ci < 2; ci++) {
                        float tq = iq + s_cbsq[colbase + n8 * 8 + ci];
                        float dist = tq - 2.0f * acc[mt][n8][hf * 2 + ci];
                        dl[(mt * 2 + hf) * 8 + n8 * 2 + ci] = dist;
                        mn = fminf(mn, dist);
                    }
                }
                mnl[mt * 2 + hf] = mn;
                float o1 = __shfl_xor_sync(0xFFFFFFFFu, mn, 1);
                mn = fminf(mn, o1);
                float o2 = __shfl_xor_sync(0xFFFFFFFFu, mn, 2);
                mn = fminf(mn, o2);
                if ((lane & 3) == 0) {
                    int row = warp_m * 32 + mt * 16 + hf * 8 + (lane >> 2);
                    if (mn < __uint_as_float(s_rowmin[row]))
                        atomicMin(&s_rowmin[row], __float_as_uint(mn));
                }
            }
        }
        #pragma unroll
        for (int i = 0; i < 4; i++) {
            const int mt = i >> 1, hf = i & 1;
            const int row = warp_m * 32 + mt * 16 + hf * 8 + (lane >> 2);
            const float thr = __uint_as_float(s_rowmin[row]) + MARGIN;
            if (mnl[i] < thr) {
                #pragma unroll
                for (int j = 0; j < 8; j++) {
                    if (dl[i * 8 + j] < thr) {
                        int pos = atomicAdd(&s_cnt[row], 1);
                        if (pos < MAXCAND)
                            s_cand[row * MAXCAND + pos] =
                                (uint32_t)(colbase + (j >> 1) * 8 + (j & 1));
                    }
                }
            }
        }
    }
    __syncthreads();

    // ---- dump candidates + counts to global (coalesced) ----
    if (t < 128) g_cnt[n0 + t] = s_cnt[t];
    #pragma unroll
    for (int i = 0; i < (128 * MAXCAND) / 512; i++)
        g_cand[(size_t)n0 * MAXCAND + i * 512 + t] = s_cand[i * 512 + t];
}

// ---------------- exact rescore (R14-best design, 16 rows / 128 threads) ------
// Stage 16 xt rows coalesced in shared; classify; queue of (row,col) pairs;
// one candidate per thread: cb row via __ldg float4 (L2-resident), xt from
// shared, bit-identical sequential d=0..255 fp32 fmaf chain. cnt==1 rows
// short-circuit. cnt > MAXCAND rows (rare/never) get a cooperative full scan.
// Also writes the one-hot 1.0f into enc (memset to zero happens first).
__global__ void __launch_bounds__(128) k_rescore(const float* __restrict__ cb,
                                                 float* __restrict__ enc) {
    __shared__ float xt_sh[16 * 257];
    __shared__ uint32_t queue[16 * MAXCAND];
    __shared__ u64 s_best[16];
    __shared__ int s_meta[2];            // [0]=qtot [1]=nfull
    __shared__ int s_full[16];
    __shared__ int s_cnts[16];

    const int t = threadIdx.x;
    const int n0 = blockIdx.x * 16;

    if (t == 0) { s_meta[0] = 0; s_meta[1] = 0; }
    if (t < 16) s_best[t] = ~0ull;
    __syncthreads();

    // stage 16 xt rows (coalesced float4): 1024 float4 over 128 threads
    #pragma unroll
    for (int j = 0; j < 8; j++) {
        int f4 = j * 128 + t;
        int row = f4 >> 6, q4 = f4 & 63;
        float4 v = *reinterpret_cast<const float4*>(
            &g_xt[(size_t)(n0 + row) * 256 + q4 * 4]);
        float* dst = &xt_sh[row * 257 + q4 * 4];
        dst[0] = v.x; dst[1] = v.y; dst[2] = v.z; dst[3] = v.w;
    }

    // classify + pack queue
    if (t < 16) {
        int n = n0 + t;
        int cnt = g_cnt[n];
        s_cnts[t] = cnt;
        if (cnt == 1) {
            int kbest = (int)g_cand[(size_t)n * MAXCAND];
            g_idx[n] = kbest;
            atomicAdd(&g_hist[kbest], 1);
            if (enc) enc[(size_t)n * NCODE + kbest] = 1.0f;
        } else if (cnt <= MAXCAND) {
            int base = atomicAdd(&s_meta[0], cnt);
            for (int i = 0; i < cnt; i++)
                queue[base + i] = ((uint32_t)t << 10) |
                                  g_cand[(size_t)n * MAXCAND + i];
        } else {
            int fi = atomicAdd(&s_meta[1], 1);
            s_full[fi] = t;
        }
    }
    __syncthreads();

    // one candidate per thread
    const int qtot = s_meta[0];
    for (int j = t; j < qtot; j += 128) {
        uint32_t e = queue[j];
        int rl = e >> 10, col = (int)(e & 1023);
        const float* xr = &xt_sh[rl * 257];
        const float4* cr4 = reinterpret_cast<const float4*>(cb + (size_t)col * 256);
        float dot = 0.f;
        #pragma unroll 8
        for (int d4 = 0; d4 < 64; d4++) {
            float4 c4 = __ldg(cr4 + d4);
            dot = fmaf(xr[d4 * 4 + 0], c4.x, dot);
            dot = fmaf(xr[d4 * 4 + 1], c4.y, dot);
            dot = fmaf(xr[d4 * 4 + 2], c4.z, dot);
            dot = fmaf(xr[d4 * 4 + 3], c4.w, dot);
        }
        float tq = g_insq[n0 + rl] + g_cbsq[col];
        float dist = tq - 2.0f * dot;
        u64 k = ((u64)__float_as_uint(dist) << 32) | (unsigned)col;
        atomicMin(&s_best[rl], k);
    }

    // full-scan fallback rows (block-cooperative; rare/never)
    const int nfull = s_meta[1];
    for (int fi = 0; fi < nfull; fi++) {
        int rl = s_full[fi];
        const float* xr = &xt_sh[rl * 257];
        const float iq = g_insq[n0 + rl];
        u64 best = ~0ull;
        for (int col = t; col < NCODE; col += 128) {
            const float4* cr4 = reinterpret_cast<const float4*>(cb + (size_t)col * 256);
            float dot = 0.f;
            #pragma unroll 8
            for (int d4 = 0; d4 < 64; d4++) {
                float4 c4 = __ldg(cr4 + d4);
                dot = fmaf(xr[d4 * 4 + 0], c4.x, dot);
                dot = fmaf(xr[d4 * 4 + 1], c4.y, dot);
                dot = fmaf(xr[d4 * 4 + 2], c4.z, dot);
                dot = fmaf(xr[d4 * 4 + 3], c4.w, dot);
            }
            float dist = (iq + g_cbsq[col]) - 2.0f * dot;
            u64 k = ((u64)__float_as_uint(dist) << 32) | (unsigned)col;
            if (k < best) best = k;
        }
        if (best != ~0ull) atomicMin(&s_best[rl], best);
    }
    __syncthreads();

    if (t < 16 && s_cnts[t] >= 2) {
        int n = n0 + t;
        int kbest = (int)(unsigned)(s_best[t] & 0xFFFFFFFFull);
        g_idx[n] = kbest;
        atomicAdd(&g_hist[kbest], 1);
        if (enc) enc[(size_t)n * NCODE + kbest] = 1.0f;
    }
}

// ---------------- outputs ----------------
// coalesced xq: block = (b, 32 hw) x 256 d; codebook rows staged in shared.
__global__ void __launch_bounds__(256) k_xq2(const float* __restrict__ x,
                                             const float* __restrict__ cb,
                                             float* __restrict__ outb) {
    __shared__ float cbs[32 * 261];
    __shared__ int idxs[32];
    __shared__ float warpsum[8];
    const int t = threadIdx.x;
    const int b = blockIdx.x >> 7;
    const int hw0 = (blockIdx.x & 127) << 5;
    const int n0 = (b << 12) + hw0;
    if (t < 32) idxs[t] = g_idx[n0 + t];
    __syncthreads();
    #pragma unroll
    for (int j = 0; j < 8; j++) {
        int lin = j * 256 + t;               // 2048 = 32 rows x 64 float4
        int row = lin >> 6, f4 = lin & 63;
        float4 v = *reinterpret_cast<const float4*>(
            &cb[(size_t)idxs[row] * 256 + f4 * 4]);
        float* dst = &cbs[row * 261 + f4 * 4];
        dst[0] = v.x; dst[1] = v.y; dst[2] = v.z; dst[3] = v.w;
    }
    __syncthreads();
    float lsum = 0.f;
    #pragma unroll
    for (int i2 = 0; i2 < 8; i2++) {
        int f4 = i2 * 256 + t;               // 2048 float4 tiles
        int d = f4 >> 3, hw4 = (f4 & 7) * 4;
        size_t gi = (((size_t)b * 256 + d) << 12) + hw0 + hw4;
        float4 xv = *reinterpret_cast<const float4*>(x + gi);
        float q0 = cbs[(hw4 + 0) * 261 + d];
        float q1 = cbs[(hw4 + 1) * 261 + d];
        float q2 = cbs[(hw4 + 2) * 261 + d];
        float q3 = cbs[(hw4 + 3) * 261 + d];
        float d0 = q0 - xv.x, d1 = q1 - xv.y, d2 = q2 - xv.z, d3 = q3 - xv.w;
        lsum += d0 * d0; lsum += d1 * d1; lsum += d2 * d2; lsum += d3 * d3;
        outb[gi]     = xv.x + d0;
        outb[gi + 1] = xv.y + d1;
        outb[gi + 2] = xv.z + d2;
        outb[gi + 3] = xv.w + d3;
    }
    #pragma unroll
    for (int off = 16; off; off >>= 1) lsum += __shfl_down_sync(0xFFFFFFFFu, lsum, off);
    if ((t & 31) == 0) warpsum[t >> 5] = lsum;
    __syncthreads();
    if (t == 0) {
        float s = 0.f;
        #pragma unroll
        for (int ww = 0; ww < 8; ww++) s += warpsum[ww];
        atomicAdd(&g_losssum, (double)s);
    }
}

__global__ void k_fin(float* __restrict__ out_loss, float* __restrict__ out_perp) {
    __shared__ float sred[32];
    int t = threadIdx.x;
    float e_mean = (float)g_hist[t] * (1.0f / 65536.0f);
    float term = e_mean * logf(e_mean + 1e10f);
    #pragma unroll
    for (int off = 16; off; off >>= 1) term += __shfl_down_sync(0xFFFFFFFFu, term, off);
    if ((t & 31) == 0) sred[t >> 5] = term;
    __syncthreads();
    if (t < 32) {
        float v = sred[t];
        #pragma unroll
        for (int off = 16; off; off >>= 1) v += __shfl_down_sync(0xFFFFFFFFu, v, off);
        if (t == 0) {
            if (out_perp) *out_perp = expf(-v);
            if (out_loss) {
                float mse = (float)(g_losssum * (1.0 / 16777216.0));
                *out_loss = mse + 0.25f * mse;
            }
        }
    }
}

extern "C" void kernel_launch(void* const* d_in, const int* in_sizes, int n_in,
                              void* d_out, int out_size) {
    const float* x  = (const float*)d_in[0];
    const float* cb = (const float*)d_in[1];
    if (n_in >= 2 && in_sizes[0] == NCODE * DIM) {
        x  = (const float*)d_in[1];
        cb = (const float*)d_in[0];
    }

    float* out = (float*)d_out;
    float *o_loss = nullptr, *o_xq = nullptr, *o_perp = nullptr, *o_enc = nullptr;
    if (out_size == XELEMS) {
        o_xq = out;
    } else if (out_size == ENCELEMS) {
        o_enc = out;
    } else if (out_size == 2) {
        o_loss = out; o_perp = out + 1;
    } else {
        o_loss = out;
        o_xq   = out + 1;
        o_perp = out + 1 + XELEMS;
        o_enc  = out + 2 + XELEMS;
    }

    cudaFuncSetAttribute(k_mma, cudaFuncAttributeMaxDynamicSharedMemorySize, SM_TOTAL);

    // memset first so k_rescore can write the one-hot 1.0s directly.
    if (o_enc) cudaMemsetAsync(o_enc, 0, (size_t)ENCELEMS * sizeof(float));
    k_prep<<<512, 256>>>(cb);
    k_split_x<<<NROWS / 32, 256>>>(x);
    k_mma<<<NROWS / 128, 512, SM_TOTAL>>>();
    k_rescore<<<NROWS / 16, 128>>>(cb, o_enc);
    if (o_xq) k_xq2<<<2048, 256>>>(x, cb, o_xq);
    k_fin<<<1, 1024>>>(o_loss, o_perp);
}